// round 7
// baseline (speedup 1.0000x reference)
#include <cuda_runtime.h>
#include <math.h>
#include <stdint.h>
#include <stddef.h>

#define BB 4
#define SQ 1024
#define EM 256
#define NH 8
#define HD 32
#define MROWS (BB*SQ)          // 4096
#define HID 128                // MLP hidden

// ---------------- scratch (static device globals; allocation-free) ----------
__device__ float g_q[BB*NH*SQ*HD];                 // (b,h,s,d) 4 MB
__device__ float g_k[BB*NH*SQ*HD];
__device__ float g_v[BB*NH*SQ*HD];
__device__ float g_hidden[MROWS*HID];              // 2 MB
__device__ float g_off[MROWS*NH*2];                // (b*S+s)*16 + h*2 + {x,y}
__device__ float g_scores[(size_t)BB*NH*SQ*SQ];    // 128 MB
__device__ float g_p[(size_t)BB*NH*SQ*SQ];         // 128 MB
__device__ float g_att[MROWS*EM];                  // (b,s, h*32+d) 4 MB

// ---------------- generic 64x64 GEMM, K=256, 4x4 per thread -----------------
// mode 0/1/2: out = x@W scattered into g_q/g_k/g_v   (N=256)
// mode 3:     out = gelu(x@W + bias) -> g_hidden     (N=128)
// mode 4:     out = g_att@W + bias -> outp           (N=256)
__global__ void gemm64_kernel(const float* __restrict__ A,
                              const float* __restrict__ W,
                              const float* __restrict__ bias,
                              float* __restrict__ outp,
                              int N, int mode) {
    __shared__ float As[64][16];
    __shared__ float Bs[16][64];
    const float* Ap = (mode == 4) ? g_att : A;
    int tm = blockIdx.x * 64;
    int tn = blockIdx.y * 64;
    int tid = threadIdx.x;
    int tx = tid & 15, ty = tid >> 4;
    float acc[4][4] = {};
    for (int k0 = 0; k0 < EM; k0 += 16) {
        int m  = tid >> 2;            // 0..63
        int kb = (tid & 3) * 4;       // 0..12
        *(float4*)&As[m][kb] = *(const float4*)&Ap[(size_t)(tm + m) * EM + k0 + kb];
        int kk = tid >> 4;            // 0..15
        int nb = (tid & 15) * 4;      // 0..60
        *(float4*)&Bs[kk][nb] = *(const float4*)&W[(size_t)(k0 + kk) * N + tn + nb];
        __syncthreads();
#pragma unroll
        for (int k = 0; k < 16; k++) {
            float a[4], bv[4];
#pragma unroll
            for (int i = 0; i < 4; i++) a[i] = As[ty * 4 + i][k];
#pragma unroll
            for (int j = 0; j < 4; j++) bv[j] = Bs[k][tx * 4 + j];
#pragma unroll
            for (int i = 0; i < 4; i++)
#pragma unroll
                for (int j = 0; j < 4; j++) acc[i][j] += a[i] * bv[j];
        }
        __syncthreads();
    }
    float* scat = (mode == 0) ? g_q : (mode == 1) ? g_k : g_v;
#pragma unroll
    for (int i = 0; i < 4; i++) {
#pragma unroll
        for (int j = 0; j < 4; j++) {
            int m = tm + ty * 4 + i;
            int n = tn + tx * 4 + j;
            float v = acc[i][j];
            if (mode < 3) {
                int b = m >> 10, s = m & 1023, h = n >> 5, d = n & 31;
                scat[(((size_t)(b * NH + h)) * SQ + s) * HD + d] = v;
            } else if (mode == 3) {
                v += bias[n];
                v = 0.5f * v * (1.0f + erff(v * 0.70710678118654752f));
                g_hidden[(size_t)m * HID + n] = v;
            } else {
                v += bias[n];
                outp[(size_t)m * EM + n] = v;
            }
        }
    }
}

// ---------------- offset MLP layer 2: (4096,128)@(128,16)+b -----------------
__global__ void off2_kernel(const float* __restrict__ W2,
                            const float* __restrict__ b2) {
    int tid = threadIdx.x;
    int o = tid & 15;           // 0..15
    int r = tid >> 4;           // 0..15
    int row = blockIdx.x * 16 + r;
    float acc = b2[o];
    const float* hrow = &g_hidden[(size_t)row * HID];
#pragma unroll 8
    for (int k = 0; k < HID; k++) acc += hrow[k] * W2[k * 16 + o];
    g_off[(size_t)row * 16 + o] = acc;
}

// ---------------- scores: per-head Q @ K^T * scale ---------------------------
__global__ void scores_kernel() {
    __shared__ float As[64][32];
    __shared__ float Bs[64][33];   // padded: kills 16-way conflicts
    int bh = blockIdx.z;
    int tm = blockIdx.x * 64;
    int tn = blockIdx.y * 64;
    const float* Q = g_q + (size_t)bh * SQ * HD;
    const float* K = g_k + (size_t)bh * SQ * HD;
    int tid = threadIdx.x;
    int tx = tid & 15, ty = tid >> 4;
    {
        int m = tid >> 2;            // 0..63
        int k8 = (tid & 3) * 8;      // 0,8,16,24
        float4 a0 = *(const float4*)&Q[(size_t)(tm + m) * HD + k8];
        float4 a1 = *(const float4*)&Q[(size_t)(tm + m) * HD + k8 + 4];
        *(float4*)&As[m][k8]     = a0;
        *(float4*)&As[m][k8 + 4] = a1;
        float4 b0 = *(const float4*)&K[(size_t)(tn + m) * HD + k8];
        float4 b1 = *(const float4*)&K[(size_t)(tn + m) * HD + k8 + 4];
        Bs[m][k8 + 0] = b0.x; Bs[m][k8 + 1] = b0.y; Bs[m][k8 + 2] = b0.z; Bs[m][k8 + 3] = b0.w;
        Bs[m][k8 + 4] = b1.x; Bs[m][k8 + 5] = b1.y; Bs[m][k8 + 6] = b1.z; Bs[m][k8 + 7] = b1.w;
    }
    __syncthreads();
    float acc[4][4] = {};
#pragma unroll
    for (int k = 0; k < 32; k++) {
        float a[4], bv[4];
#pragma unroll
        for (int i = 0; i < 4; i++) a[i] = As[ty * 4 + i][k];
#pragma unroll
        for (int j = 0; j < 4; j++) bv[j] = Bs[tx * 4 + j][k];
#pragma unroll
        for (int i = 0; i < 4; i++)
#pragma unroll
            for (int j = 0; j < 4; j++) acc[i][j] += a[i] * bv[j];
    }
    const float scale = 0.17677669529663687f;   // 1/sqrt(32)
    float* out = g_scores + (size_t)bh * SQ * SQ;
#pragma unroll
    for (int i = 0; i < 4; i++)
#pragma unroll
        for (int j = 0; j < 4; j++)
            out[(size_t)(tm + ty * 4 + i) * SQ + tn + tx * 4 + j] = acc[i][j] * scale;
}

// ------------- deform (bilinear on scores) + softmax -> g_p ------------------
__global__ void deform_softmax_kernel() {
    __shared__ float sd[SQ];
    __shared__ float red[256];
    int blk = blockIdx.x;
    int bh = blk >> 10;
    int i  = blk & 1023;
    int b = bh >> 3, h = bh & 7;
    int tid = threadIdx.x;

    float ox = g_off[((size_t)(b * SQ + i)) * 16 + h * 2 + 0];
    float oy = g_off[((size_t)(b * SQ + i)) * 16 + h * 2 + 1];

    float ysf = (float)i + oy;
    float y0f = floorf(ysf);
    float wy  = ysf - y0f;
    int   y0  = (int)y0f;
    const float lim = 1023.0f;
    bool vy0 = (y0f >= 0.0f) && (y0f <= lim);
    bool vy1 = (y0f + 1.0f >= 0.0f) && (y0f + 1.0f <= lim);
    const float* srow = g_scores + (size_t)bh * SQ * SQ;
    const float* r0 = srow + (ptrdiff_t)y0 * SQ;
    const float* r1 = r0 + SQ;

    float lmax = -3.4e38f;
#pragma unroll
    for (int jj = 0; jj < 4; jj++) {
        int j = tid + jj * 256;
        float xsf = (float)j + ox;
        float x0f = floorf(xsf);
        float wx  = xsf - x0f;
        int   x0  = (int)x0f;
        bool vx0 = (x0f >= 0.0f) && (x0f <= lim);
        bool vx1 = (x0f + 1.0f >= 0.0f) && (x0f + 1.0f <= lim);
        float v00 = (vy0 && vx0) ? r0[x0]     : 0.0f;
        float v01 = (vy0 && vx1) ? r0[x0 + 1] : 0.0f;
        float v10 = (vy1 && vx0) ? r1[x0]     : 0.0f;
        float v11 = (vy1 && vx1) ? r1[x0 + 1] : 0.0f;
        float dv = v00 * (1.0f - wy) * (1.0f - wx)
                 + v01 * (1.0f - wy) * wx
                 + v10 * wy * (1.0f - wx)
                 + v11 * wy * wx;
        sd[j] = dv;
        lmax = fmaxf(lmax, dv);
    }
    red[tid] = lmax;
    __syncthreads();
    for (int s = 128; s > 0; s >>= 1) {
        if (tid < s) red[tid] = fmaxf(red[tid], red[tid + s]);
        __syncthreads();
    }
    float bmax = red[0];
    __syncthreads();
    float lsum = 0.0f;
#pragma unroll
    for (int jj = 0; jj < 4; jj++) {
        int j = tid + jj * 256;
        float e = expf(sd[j] - bmax);
        sd[j] = e;
        lsum += e;
    }
    red[tid] = lsum;
    __syncthreads();
    for (int s = 128; s > 0; s >>= 1) {
        if (tid < s) red[tid] += red[tid + s];
        __syncthreads();
    }
    float inv = 1.0f / red[0];
    float* prow = g_p + (size_t)bh * SQ * SQ + (size_t)i * SQ;
#pragma unroll
    for (int jj = 0; jj < 4; jj++) {
        int j = tid + jj * 256;
        prow[j] = sd[j] * inv;
    }
}

// ---------------- AV: per-head P(1024,1024) @ V(1024,32) ---------------------
__global__ void av_kernel() {
    __shared__ float Ps[64][33];
    __shared__ float Vs[32][32];
    int bh = blockIdx.y;
    int tm = blockIdx.x * 64;
    const float* P = g_p + (size_t)bh * SQ * SQ;
    const float* V = g_v + (size_t)bh * SQ * HD;
    int tid = threadIdx.x;        // 128 threads
    int tx = tid & 7;             // 4 cols each
    int ty = tid >> 3;            // 0..15, rows ty+16q
    float acc[4][4] = {};
    for (int k0 = 0; k0 < SQ; k0 += 32) {
        int m  = tid >> 1;            // 0..63
        int kb = (tid & 1) * 16;
#pragma unroll
        for (int q = 0; q < 4; q++) {
            float4 p4 = *(const float4*)&P[(size_t)(tm + m) * SQ + k0 + kb + q * 4];
            Ps[m][kb + q * 4 + 0] = p4.x;
            Ps[m][kb + q * 4 + 1] = p4.y;
            Ps[m][kb + q * 4 + 2] = p4.z;
            Ps[m][kb + q * 4 + 3] = p4.w;
        }
        int kv = tid >> 2;            // 0..31
        int db = (tid & 3) * 8;
        float4 v0 = *(const float4*)&V[(size_t)(k0 + kv) * HD + db];
        float4 v1 = *(const float4*)&V[(size_t)(k0 + kv) * HD + db + 4];
        *(float4*)&Vs[kv][db]     = v0;
        *(float4*)&Vs[kv][db + 4] = v1;
        __syncthreads();
#pragma unroll
        for (int k = 0; k < 32; k++) {
            float4 v = *(const float4*)&Vs[k][tx * 4];
#pragma unroll
            for (int q = 0; q < 4; q++) {
                float p = Ps[ty + 16 * q][k];
                acc[q][0] += p * v.x;
                acc[q][1] += p * v.y;
                acc[q][2] += p * v.z;
                acc[q][3] += p * v.w;
            }
        }
        __syncthreads();
    }
    int b = bh >> 3, h = bh & 7;
#pragma unroll
    for (int q = 0; q < 4; q++) {
        int s = tm + ty + 16 * q;
#pragma unroll
        for (int j = 0; j < 4; j++) {
            g_att[((size_t)(b * SQ + s)) * EM + h * HD + tx * 4 + j] = acc[q][j];
        }
    }
}

// ----------------------------- launcher --------------------------------------
extern "C" void kernel_launch(void* const* d_in, const int* in_sizes, int n_in,
                              void* d_out, int out_size) {
    const float* x      = (const float*)d_in[0];
    const float* Wq     = (const float*)d_in[1];
    const float* Wk     = (const float*)d_in[2];
    const float* Wv     = (const float*)d_in[3];
    const float* W_off1 = (const float*)d_in[4];
    const float* b_off1 = (const float*)d_in[5];
    const float* W_off2 = (const float*)d_in[6];
    const float* b_off2 = (const float*)d_in[7];
    const float* W_out  = (const float*)d_in[8];
    const float* b_out  = (const float*)d_in[9];
    float* out = (float*)d_out;

    // 1) QKV projections (scatter to (b,h,s,d))
    gemm64_kernel<<<dim3(MROWS / 64, EM / 64), 256>>>(x, Wq, nullptr, nullptr, EM, 0);
    gemm64_kernel<<<dim3(MROWS / 64, EM / 64), 256>>>(x, Wk, nullptr, nullptr, EM, 1);
    gemm64_kernel<<<dim3(MROWS / 64, EM / 64), 256>>>(x, Wv, nullptr, nullptr, EM, 2);

    // 2) offset MLP
    gemm64_kernel<<<dim3(MROWS / 64, HID / 64), 256>>>(x, W_off1, b_off1, nullptr, HID, 3);
    off2_kernel<<<MROWS / 16, 256>>>(W_off2, b_off2);

    // 3) scores = QK^T * scale
    scores_kernel<<<dim3(SQ / 64, SQ / 64, BB * NH), 256>>>();

    // 4) deformable bilinear sample + softmax
    deform_softmax_kernel<<<BB * NH * SQ, 256>>>();

    // 5) attn @ V
    av_kernel<<<dim3(SQ / 64, BB * NH), 128>>>();

    // 6) output projection + bias
    gemm64_kernel<<<dim3(MROWS / 64, EM / 64), 256>>>(nullptr, W_out, b_out, out, EM, 4);
}